// round 1
// baseline (speedup 1.0000x reference)
#include <cuda_runtime.h>
#include <cstddef>

// ---------------------------------------------------------------------------
// Problem constants (from reference): B=8, S=1024, D=512, H=8, DK=D=512.
// ---------------------------------------------------------------------------
#define B_    8
#define S_    1024
#define D_    512
#define H_    8
#define DK_   512
#define HD_   4096          // H_*DK_

// ---------------------------------------------------------------------------
// Scratch (device globals; no runtime allocation allowed).
//   g_qh/g_kh/g_vh : (B,H,S,DK)  = 33,554,432 floats each (134 MB)
//   g_sc           : (B*H,S,S)   = 67,108,864 floats      (268 MB)
//   g_att          : (B,S,H*DK)  = 33,554,432 floats      (134 MB)
// ---------------------------------------------------------------------------
__device__ float g_qh[(size_t)B_ * H_ * S_ * DK_];
__device__ float g_kh[(size_t)B_ * H_ * S_ * DK_];
__device__ float g_vh[(size_t)B_ * H_ * S_ * DK_];
__device__ float g_sc[(size_t)B_ * H_ * S_ * S_];
__device__ float g_att[(size_t)B_ * S_ * HD_];

// ---------------------------------------------------------------------------
// Tiled SGEMM: C = A @ B (or A @ B^T), 128x128 tile, BK=8, 256 threads,
// 8x8 per-thread register block. All problem dims here are multiples of the
// tile sizes, so no bounds checks are needed.
//
// TRANSB = true : Bmat is [N,K] row-major (weight layout), C[m,n] = sum_k A[m,k]*Bmat[n,k]
// TRANSB = false: Bmat is [K,N] row-major,                 C[m,n] = sum_k A[m,k]*Bmat[k,n]
//
// EPI:
//   0 = plain batched store with scale          (scores)
//   1 = permute (B,S,H*DK) -> (B,H,S,DK)        (projections)
//   2 = permute (bh batch, S, DK) -> (B,S,H*DK) (P@V output)
//   3 = add residual, plain store               (fc)
// ---------------------------------------------------------------------------
#define BM 128
#define BN 128
#define BKK 8
#define TM 8
#define TN 8

template <bool TRANSB, int EPI>
__global__ void __launch_bounds__(256)
gemm_k(const float* __restrict__ A0, const float* __restrict__ B0,
       float* __restrict__ C0, const float* __restrict__ resid,
       int M, int N, int K,
       size_t strideA, size_t strideB, size_t strideC, float scale)
{
    __shared__ float As[BKK][BM];
    __shared__ float Bs[BKK][BN];

    const int tid = threadIdx.x;
    const int z   = blockIdx.z;

    const float* A  = A0 + (size_t)z * strideA;
    const float* Bm = B0 + (size_t)z * strideB;

    const int m0 = blockIdx.y * BM;
    const int n0 = blockIdx.x * BN;

    const int tx = tid & 15;        // 0..15 -> column group
    const int ty = tid >> 4;        // 0..15 -> row group

    // loader indices
    const int lr  = tid >> 1;       // 0..127 (row of A tile / row of W tile)
    const int lc  = (tid & 1) * 4;  // 0 or 4 (k offset)
    const int bkr = tid >> 5;       // 0..7   (k row, no-trans B)
    const int bnc = (tid & 31) * 4; // 0..124 (n col, no-trans B)

    float acc[TM][TN];
#pragma unroll
    for (int i = 0; i < TM; i++)
#pragma unroll
        for (int j = 0; j < TN; j++) acc[i][j] = 0.0f;

    for (int k0 = 0; k0 < K; k0 += BKK) {
        // load A tile (transposed into As[k][m])
        float4 av = *reinterpret_cast<const float4*>(&A[(size_t)(m0 + lr) * K + k0 + lc]);
        As[lc + 0][lr] = av.x;
        As[lc + 1][lr] = av.y;
        As[lc + 2][lr] = av.z;
        As[lc + 3][lr] = av.w;

        if (TRANSB) {
            float4 bv = *reinterpret_cast<const float4*>(&Bm[(size_t)(n0 + lr) * K + k0 + lc]);
            Bs[lc + 0][lr] = bv.x;
            Bs[lc + 1][lr] = bv.y;
            Bs[lc + 2][lr] = bv.z;
            Bs[lc + 3][lr] = bv.w;
        } else {
            float4 bv = *reinterpret_cast<const float4*>(&Bm[(size_t)(k0 + bkr) * N + n0 + bnc]);
            *reinterpret_cast<float4*>(&Bs[bkr][bnc]) = bv;
        }
        __syncthreads();

#pragma unroll
        for (int kk = 0; kk < BKK; kk++) {
            float ar[TM], br[TN];
#pragma unroll
            for (int i = 0; i < TM; i++) ar[i] = As[kk][ty * TM + i];
#pragma unroll
            for (int j = 0; j < TN; j++) br[j] = Bs[kk][tx * TN + j];
#pragma unroll
            for (int i = 0; i < TM; i++)
#pragma unroll
                for (int j = 0; j < TN; j++)
                    acc[i][j] = fmaf(ar[i], br[j], acc[i][j]);
        }
        __syncthreads();
    }

    // -------- epilogue --------
    float* C = C0 + (size_t)z * strideC;

#pragma unroll
    for (int i = 0; i < TM; i++) {
        const int m = m0 + ty * TM + i;
#pragma unroll
        for (int j = 0; j < TN; j += 4) {
            const int n = n0 + tx * TN + j;
            float4 v = make_float4(acc[i][j + 0] * scale,
                                   acc[i][j + 1] * scale,
                                   acc[i][j + 2] * scale,
                                   acc[i][j + 3] * scale);
            if constexpr (EPI == 0) {
                *reinterpret_cast<float4*>(&C[(size_t)m * N + n]) = v;
            } else if constexpr (EPI == 1) {
                // m = b*S+s in [0,8192), n = h*DK+d in [0,4096)
                const int b = m >> 10, s = m & (S_ - 1);
                const int h = n >> 9,  d = n & (DK_ - 1);
                *reinterpret_cast<float4*>(
                    &C[(((size_t)(b * H_ + h)) * S_ + s) * DK_ + d]) = v;
            } else if constexpr (EPI == 2) {
                // z = b*H+h, m = s, n = d
                const int b = z >> 3, h = z & (H_ - 1);
                *reinterpret_cast<float4*>(
                    &C[((size_t)(b * S_ + m)) * HD_ + h * DK_ + n]) = v;
            } else { // EPI == 3 : residual add
                const float* r = &resid[(size_t)m * N + n];
                v.x += r[0]; v.y += r[1]; v.z += r[2]; v.w += r[3];
                *reinterpret_cast<float4*>(&C[(size_t)m * N + n]) = v;
            }
        }
    }
}

// ---------------------------------------------------------------------------
// Row softmax over length-1024 rows. One block (256 threads) per row.
// ---------------------------------------------------------------------------
__global__ void __launch_bounds__(256) softmax_k(float* __restrict__ sc)
{
    const size_t row = blockIdx.x;
    float4* p = reinterpret_cast<float4*>(sc) + row * 256 + threadIdx.x;
    float4 v = *p;

    __shared__ float red[8];

    float m = fmaxf(fmaxf(v.x, v.y), fmaxf(v.z, v.w));
#pragma unroll
    for (int o = 16; o; o >>= 1) m = fmaxf(m, __shfl_xor_sync(0xffffffffu, m, o));
    if ((threadIdx.x & 31) == 0) red[threadIdx.x >> 5] = m;
    __syncthreads();
    m = red[0];
#pragma unroll
    for (int i = 1; i < 8; i++) m = fmaxf(m, red[i]);

    v.x = expf(v.x - m); v.y = expf(v.y - m);
    v.z = expf(v.z - m); v.w = expf(v.w - m);

    float s = v.x + v.y + v.z + v.w;
#pragma unroll
    for (int o = 16; o; o >>= 1) s += __shfl_xor_sync(0xffffffffu, s, o);
    __syncthreads();                 // protect red[] reuse
    if ((threadIdx.x & 31) == 0) red[threadIdx.x >> 5] = s;
    __syncthreads();
    s = 0.0f;
#pragma unroll
    for (int i = 0; i < 8; i++) s += red[i];

    const float inv = 1.0f / s;
    v.x *= inv; v.y *= inv; v.z *= inv; v.w *= inv;
    *p = v;
}

// ---------------------------------------------------------------------------
// LayerNorm over length-512 rows, in-place on d_out. One block per row.
// ---------------------------------------------------------------------------
__global__ void __launch_bounds__(256) ln_k(float* __restrict__ out,
                                            const float* __restrict__ gamma,
                                            const float* __restrict__ beta)
{
    const size_t row = blockIdx.x;
    float2* p = reinterpret_cast<float2*>(out) + row * 256 + threadIdx.x;
    float2 v = *p;

    float s  = v.x + v.y;
    float ss = v.x * v.x + v.y * v.y;

    __shared__ float r1[8], r2[8];
#pragma unroll
    for (int o = 16; o; o >>= 1) {
        s  += __shfl_xor_sync(0xffffffffu, s, o);
        ss += __shfl_xor_sync(0xffffffffu, ss, o);
    }
    if ((threadIdx.x & 31) == 0) { r1[threadIdx.x >> 5] = s; r2[threadIdx.x >> 5] = ss; }
    __syncthreads();
    s = 0.0f; ss = 0.0f;
#pragma unroll
    for (int i = 0; i < 8; i++) { s += r1[i]; ss += r2[i]; }

    const float mu  = s * (1.0f / 512.0f);
    const float var = ss * (1.0f / 512.0f) - mu * mu;
    const float inv = rsqrtf(var + 1e-6f);

    const int c = threadIdx.x * 2;
    v.x = (v.x - mu) * inv * gamma[c + 0] + beta[c + 0];
    v.y = (v.y - mu) * inv * gamma[c + 1] + beta[c + 1];
    *p = v;
}

// ---------------------------------------------------------------------------
// Launch. Inputs (metadata order): q,k,v,w_q,w_k,w_v,w_fc,gamma,beta.
// Output: fp32 (B,S,D) = 8192x512.
// ---------------------------------------------------------------------------
extern "C" void kernel_launch(void* const* d_in, const int* in_sizes, int n_in,
                              void* d_out, int out_size)
{
    const float* in_q  = (const float*)d_in[0];
    const float* in_k  = (const float*)d_in[1];
    const float* in_v  = (const float*)d_in[2];
    const float* w_q   = (const float*)d_in[3];
    const float* w_k   = (const float*)d_in[4];
    const float* w_v   = (const float*)d_in[5];
    const float* w_fc  = (const float*)d_in[6];
    const float* gamma = (const float*)d_in[7];
    const float* beta  = (const float*)d_in[8];
    float* out = (float*)d_out;

    float *qh, *kh, *vh, *sc, *att;
    cudaGetSymbolAddress((void**)&qh,  g_qh);
    cudaGetSymbolAddress((void**)&kh,  g_kh);
    cudaGetSymbolAddress((void**)&vh,  g_vh);
    cudaGetSymbolAddress((void**)&sc,  g_sc);
    cudaGetSymbolAddress((void**)&att, g_att);

    const dim3 blk(256);
    const float SCALE = 0.044194173824159216f;   // 1/sqrt(512)

    // 1) Projections: (8192x512)@(512x4096)^T -> permuted to (B,H,S,DK)
    const dim3 gp(HD_ / BN, (B_ * S_) / BM, 1);
    gemm_k<true, 1><<<gp, blk>>>(in_q, w_q, qh, nullptr, B_ * S_, HD_, D_, 0, 0, 0, 1.0f);
    gemm_k<true, 1><<<gp, blk>>>(in_k, w_k, kh, nullptr, B_ * S_, HD_, D_, 0, 0, 0, 1.0f);
    gemm_k<true, 1><<<gp, blk>>>(in_v, w_v, vh, nullptr, B_ * S_, HD_, D_, 0, 0, 0, 1.0f);

    // 2) Scores: per (b,h), (1024x512)@(1024x512)^T * scale
    const dim3 gs(S_ / BN, S_ / BM, B_ * H_);
    gemm_k<true, 0><<<gs, blk>>>(qh, kh, sc, nullptr, S_, S_, DK_,
                                 (size_t)S_ * DK_, (size_t)S_ * DK_,
                                 (size_t)S_ * S_, SCALE);

    // 3) Row softmax over 64*1024 rows of 1024
    softmax_k<<<B_ * H_ * S_, 256>>>(sc);

    // 4) P@V: per (b,h), (1024x1024)@(1024x512) -> permuted to (B,S,H*DK)
    const dim3 gv(DK_ / BN, S_ / BM, B_ * H_);
    gemm_k<false, 2><<<gv, blk>>>(sc, vh, att, nullptr, S_, DK_, S_,
                                  (size_t)S_ * S_, (size_t)S_ * DK_, 0, 1.0f);

    // 5) fc: (8192x4096)@(512x4096)^T + residual -> d_out
    const dim3 gf(D_ / BN, (B_ * S_) / BM, 1);
    gemm_k<true, 3><<<gf, blk>>>(att, w_fc, out, in_q, B_ * S_, D_, HD_, 0, 0, 0, 1.0f);

    // 6) LayerNorm in-place on d_out
    ln_k<<<B_ * S_, 256>>>(out, gamma, beta);
}